// round 12
// baseline (speedup 1.0000x reference)
#include <cuda_runtime.h>
#include <cuda_bf16.h>
#include <math.h>
#include <float.h>
#include <stdint.h>

#define N_NODES 100000
#define E_MAX   1600000
#define IN_F    512
#define HID_F   128
#define OUT_F   40
#define N2_PAD  64

#define SCAN_B  1024
#define N_SCAN_BLOCKS ((N_NODES + SCAN_B - 1) / SCAN_B)   // 98

// ---------------- scratch (device globals; no allocation allowed) ----------------
__device__ int   d_deg    [N_NODES];
__device__ int   d_rowptr [N_NODES + 1];
__device__ int   d_cursor [N_NODES];
__device__ int   d_csr_src[E_MAX];
__device__ int   d_blocksum[N_SCAN_BLOCKS];
__device__ int   d_blockoff[N_SCAN_BLOCKS + 1];
__device__ float d_dinv[N_NODES];
__device__ float d_g1  [(size_t)N_NODES * HID_F];   // raw h1 = X@W1 (unscaled)
__device__ float d_a1  [(size_t)N_NODES * HID_F];
__device__ float d_g2  [(size_t)N_NODES * OUT_F];
__device__ __nv_bfloat16 d_w1t_hi[(size_t)HID_F * IN_F];   // [n][k]
__device__ __nv_bfloat16 d_w1t_lo[(size_t)HID_F * IN_F];
__device__ __nv_bfloat16 d_w2t_hi[(size_t)N2_PAD * HID_F]; // [n][k], zero-padded n>=40
__device__ __nv_bfloat16 d_w2t_lo[(size_t)N2_PAD * HID_F];

// ---------------- helpers ----------------
__device__ __forceinline__ uint32_t smem_u32(const void* p) {
    uint32_t a;
    asm("{ .reg .u64 t; cvta.to.shared.u64 t, %1; cvt.u32.u64 %0, t; }" : "=r"(a) : "l"(p));
    return a;
}
__device__ __forceinline__ void ldmatrix_x4(uint32_t* d, uint32_t addr) {
    asm volatile("ldmatrix.sync.aligned.m8n8.x4.shared.b16 {%0,%1,%2,%3}, [%4];"
                 : "=r"(d[0]), "=r"(d[1]), "=r"(d[2]), "=r"(d[3]) : "r"(addr));
}
__device__ __forceinline__ void mma_bf16(float* c, const uint32_t* a, uint32_t b0, uint32_t b1) {
    asm volatile("mma.sync.aligned.m16n8k16.row.col.f32.bf16.bf16.f32 "
                 "{%0,%1,%2,%3}, {%4,%5,%6,%7}, {%8,%9}, {%0,%1,%2,%3};"
                 : "+f"(c[0]), "+f"(c[1]), "+f"(c[2]), "+f"(c[3])
                 : "r"(a[0]), "r"(a[1]), "r"(a[2]), "r"(a[3]), "r"(b0), "r"(b1));
}

// ---------------- CSR chain kernels (side stream) ----------------
__global__ void zero_deg_kernel() {
    int i = blockIdx.x * blockDim.x + threadIdx.x;
    if (i < N_NODES) d_deg[i] = 0;
}

__global__ void count_deg_kernel(const int* __restrict__ dst, int E) {
    int i = blockIdx.x * blockDim.x + threadIdx.x;
    int stride = gridDim.x * blockDim.x;
    for (; i < E; i += stride) atomicAdd(&d_deg[dst[i]], 1);
}

__global__ __launch_bounds__(SCAN_B) void dinv_blocksum_kernel() {
    __shared__ int sh[SCAN_B / 32];
    int i = blockIdx.x * SCAN_B + threadIdx.x;
    int v = 0;
    if (i < N_NODES) {
        v = d_deg[i];
        d_dinv[i] = rsqrtf((float)v + 1.0f);
    }
    int s = v;
#pragma unroll
    for (int o = 16; o > 0; o >>= 1) s += __shfl_xor_sync(0xFFFFFFFFu, s, o);
    if ((threadIdx.x & 31) == 0) sh[threadIdx.x >> 5] = s;
    __syncthreads();
    if (threadIdx.x < SCAN_B / 32) {
        int t = sh[threadIdx.x];
#pragma unroll
        for (int o = 16; o > 0; o >>= 1) t += __shfl_xor_sync(0xFFFFFFFFu, t, o);
        if (threadIdx.x == 0) d_blocksum[blockIdx.x] = t;
    }
}

__global__ __launch_bounds__(128) void scan_tops_kernel() {
    __shared__ int sh[N_SCAN_BLOCKS];
    int tid = threadIdx.x;
    if (tid < N_SCAN_BLOCKS) sh[tid] = d_blocksum[tid];
    __syncthreads();
    if (tid == 0) {
        int run = 0;
        for (int i = 0; i < N_SCAN_BLOCKS; i++) { int t = sh[i]; sh[i] = run; run += t; }
        d_blockoff[N_SCAN_BLOCKS] = run;
    }
    __syncthreads();
    if (tid < N_SCAN_BLOCKS) d_blockoff[tid] = sh[tid];
}

__global__ __launch_bounds__(SCAN_B) void rowptr_kernel() {
    __shared__ int sh[SCAN_B];
    int tid = threadIdx.x;
    int i = blockIdx.x * SCAN_B + tid;
    int v = (i < N_NODES) ? d_deg[i] : 0;
    sh[tid] = v;
    __syncthreads();
    for (int off = 1; off < SCAN_B; off <<= 1) {
        int t = (tid >= off) ? sh[tid - off] : 0;
        __syncthreads();
        sh[tid] += t;
        __syncthreads();
    }
    if (i < N_NODES) {
        int excl = sh[tid] - v;
        d_rowptr[i] = d_blockoff[blockIdx.x] + excl;
        d_cursor[i] = 0;
    }
    if (i == N_NODES - 1) d_rowptr[N_NODES] = d_blockoff[N_SCAN_BLOCKS];
}

__global__ void fill_kernel(const int* __restrict__ src, const int* __restrict__ dst, int E) {
    int i = blockIdx.x * blockDim.x + threadIdx.x;
    int stride = gridDim.x * blockDim.x;
    for (; i < E; i += stride) {
        int d = dst[i];
        int pos = d_rowptr[d] + atomicAdd(&d_cursor[d], 1);
        d_csr_src[pos] = src[i];
    }
}

// ---------------- weight splits (main stream, feeds gemm1/gemm2) ----------------
__global__ void prep_w_kernel(const float* __restrict__ W1, const float* __restrict__ W2) {
    int b = blockIdx.x;
    if (b < 256) {
        int i = b * blockDim.x + threadIdx.x;   // 0..65535
        int k = i / HID_F, n = i % HID_F;
        float v = W1[i];
        __nv_bfloat16 hi = __float2bfloat16(v);
        d_w1t_hi[(size_t)n * IN_F + k] = hi;
        d_w1t_lo[(size_t)n * IN_F + k] = __float2bfloat16(v - __bfloat162float(hi));
    } else {
        int i = (b - 256) * blockDim.x + threadIdx.x;  // 0..8191
        int k = i / N2_PAD, n = i % N2_PAD;
        float v = (n < OUT_F) ? W2[k * OUT_F + n] : 0.f;
        __nv_bfloat16 hi = __float2bfloat16(v);
        d_w2t_hi[(size_t)n * HID_F + k] = hi;
        d_w2t_lo[(size_t)n * HID_F + k] = __float2bfloat16(v - __bfloat162float(hi));
    }
}

// ---------------- GEMM1 (mma.sync bf16, 3-pass): h1 = X @ W1 (no dinv) ----------------
#define PK 40
#define GEMM1_BLOCKS ((N_NODES + 127) / 128)       // 782
__global__ __launch_bounds__(256, 2) void gemm1_mma_kernel(const float* __restrict__ X) {
    __shared__ __nv_bfloat16 sAh[128 * PK], sAl[128 * PK];
    __shared__ __nv_bfloat16 sBh[128 * PK], sBl[128 * PK];

    const int tid  = threadIdx.x;
    const int lane = tid & 31;
    const int w    = tid >> 5;
    const int wm   = w & 3;
    const int wn   = w >> 2;
    const int block_row = blockIdx.x * 128;

    const uint32_t uAh = smem_u32(sAh), uAl = smem_u32(sAl);
    const uint32_t uBh = smem_u32(sBh), uBl = smem_u32(sBl);

    float acc[2][8][4];
#pragma unroll
    for (int mt = 0; mt < 2; mt++)
#pragma unroll
        for (int nt = 0; nt < 8; nt++)
#pragma unroll
            for (int j = 0; j < 4; j++) acc[mt][nt][j] = 0.f;

    for (int kt = 0; kt < IN_F / 32; kt++) {
        __syncthreads();
#pragma unroll
        for (int i = 0; i < 4; i++) {
            int q  = tid + i * 256;
            int r  = q >> 3;
            int c4 = (q & 7) * 4;
            int grow = block_row + r;
            float4 v = make_float4(0.f, 0.f, 0.f, 0.f);
            if (grow < N_NODES)
                v = *(const float4*)(X + (size_t)grow * IN_F + kt * 32 + c4);
            __nv_bfloat162 h01, h23, l01, l23;
            h01.x = __float2bfloat16(v.x); h01.y = __float2bfloat16(v.y);
            h23.x = __float2bfloat16(v.z); h23.y = __float2bfloat16(v.w);
            l01.x = __float2bfloat16(v.x - __bfloat162float(h01.x));
            l01.y = __float2bfloat16(v.y - __bfloat162float(h01.y));
            l23.x = __float2bfloat16(v.z - __bfloat162float(h23.x));
            l23.y = __float2bfloat16(v.w - __bfloat162float(h23.y));
            *(__nv_bfloat162*)&sAh[r * PK + c4]     = h01;
            *(__nv_bfloat162*)&sAh[r * PK + c4 + 2] = h23;
            *(__nv_bfloat162*)&sAl[r * PK + c4]     = l01;
            *(__nv_bfloat162*)&sAl[r * PK + c4 + 2] = l23;
        }
#pragma unroll
        for (int i = 0; i < 2; i++) {
            int q  = tid + i * 256;
            int n  = q >> 2;
            int kk = (q & 3) * 8;
            uint4 hv = *(const uint4*)(d_w1t_hi + (size_t)n * IN_F + kt * 32 + kk);
            uint4 lv = *(const uint4*)(d_w1t_lo + (size_t)n * IN_F + kt * 32 + kk);
            *(uint4*)&sBh[n * PK + kk] = hv;
            *(uint4*)&sBl[n * PK + kk] = lv;
        }
        __syncthreads();

#pragma unroll
        for (int ks = 0; ks < 2; ks++) {
            uint32_t ah[2][4], al[2][4];
#pragma unroll
            for (int mt = 0; mt < 2; mt++) {
                int row  = wm * 32 + mt * 16 + (lane & 15);
                int koff = ks * 16 + (lane >> 4) * 8;
                uint32_t off = (uint32_t)(row * PK + koff) * 2;
                ldmatrix_x4(ah[mt], uAh + off);
                ldmatrix_x4(al[mt], uAl + off);
            }
#pragma unroll
            for (int g = 0; g < 4; g++) {
                int n    = wn * 64 + g * 16 + ((lane >> 4) & 1) * 8 + (lane & 7);
                int koff = ks * 16 + ((lane >> 3) & 1) * 8;
                uint32_t off = (uint32_t)(n * PK + koff) * 2;
                uint32_t bh[4], bl[4];
                ldmatrix_x4(bh, uBh + off);
                ldmatrix_x4(bl, uBl + off);
#pragma unroll
                for (int t = 0; t < 2; t++) {
                    int nt = 2 * g + t;
#pragma unroll
                    for (int mt = 0; mt < 2; mt++) {
                        mma_bf16(acc[mt][nt], ah[mt], bh[2 * t], bh[2 * t + 1]);
                        mma_bf16(acc[mt][nt], ah[mt], bl[2 * t], bl[2 * t + 1]);
                        mma_bf16(acc[mt][nt], al[mt], bh[2 * t], bh[2 * t + 1]);
                    }
                }
            }
        }
    }

#pragma unroll
    for (int mt = 0; mt < 2; mt++) {
        int r0 = block_row + wm * 32 + mt * 16 + (lane >> 2);
        int r1 = r0 + 8;
#pragma unroll
        for (int nt = 0; nt < 8; nt++) {
            int col = wn * 64 + nt * 8 + (lane & 3) * 2;
            if (r0 < N_NODES) {
                float2 o = make_float2(acc[mt][nt][0], acc[mt][nt][1]);
                *(float2*)(d_g1 + (size_t)r0 * HID_F + col) = o;
            }
            if (r1 < N_NODES) {
                float2 o = make_float2(acc[mt][nt][2], acc[mt][nt][3]);
                *(float2*)(d_g1 + (size_t)r1 * HID_F + col) = o;
            }
        }
    }
}

// ---------------- gather1: a1 = relu(dinv_d*(sum dinv_s*h1[s] + dinv_d*h1[d]) + b1) ----------------
__global__ __launch_bounds__(256) void gather1_kernel(const float* __restrict__ b1) {
    int n    = (blockIdx.x * blockDim.x + threadIdx.x) >> 5;
    int lane = threadIdx.x & 31;
    if (n >= N_NODES) return;
    int e   = d_rowptr[n];
    int end = d_rowptr[n + 1];

    const float4* G = (const float4*)d_g1;
    float4 a0 = make_float4(0.f, 0.f, 0.f, 0.f);
    float4 a1v = make_float4(0.f, 0.f, 0.f, 0.f);
    float4 a2 = make_float4(0.f, 0.f, 0.f, 0.f);
    float4 a3 = make_float4(0.f, 0.f, 0.f, 0.f);

    for (; e + 3 < end; e += 4) {
        int s0 = d_csr_src[e];
        int s1 = d_csr_src[e + 1];
        int s2 = d_csr_src[e + 2];
        int s3 = d_csr_src[e + 3];
        float ds0 = d_dinv[s0], ds1 = d_dinv[s1], ds2 = d_dinv[s2], ds3 = d_dinv[s3];
        float4 v0 = G[(size_t)s0 * 32 + lane];
        float4 v1 = G[(size_t)s1 * 32 + lane];
        float4 v2 = G[(size_t)s2 * 32 + lane];
        float4 v3 = G[(size_t)s3 * 32 + lane];
        a0.x = fmaf(v0.x, ds0, a0.x); a0.y = fmaf(v0.y, ds0, a0.y);
        a0.z = fmaf(v0.z, ds0, a0.z); a0.w = fmaf(v0.w, ds0, a0.w);
        a1v.x = fmaf(v1.x, ds1, a1v.x); a1v.y = fmaf(v1.y, ds1, a1v.y);
        a1v.z = fmaf(v1.z, ds1, a1v.z); a1v.w = fmaf(v1.w, ds1, a1v.w);
        a2.x = fmaf(v2.x, ds2, a2.x); a2.y = fmaf(v2.y, ds2, a2.y);
        a2.z = fmaf(v2.z, ds2, a2.z); a2.w = fmaf(v2.w, ds2, a2.w);
        a3.x = fmaf(v3.x, ds3, a3.x); a3.y = fmaf(v3.y, ds3, a3.y);
        a3.z = fmaf(v3.z, ds3, a3.z); a3.w = fmaf(v3.w, ds3, a3.w);
    }
    for (; e < end; e++) {
        int s0 = d_csr_src[e];
        float ds0 = d_dinv[s0];
        float4 v0 = G[(size_t)s0 * 32 + lane];
        a0.x = fmaf(v0.x, ds0, a0.x); a0.y = fmaf(v0.y, ds0, a0.y);
        a0.z = fmaf(v0.z, ds0, a0.z); a0.w = fmaf(v0.w, ds0, a0.w);
    }
    float4 self = G[(size_t)n * 32 + lane];
    float dv = d_dinv[n];
    float4 b = *(const float4*)(b1 + lane * 4);
    float4 o;
    o.x = fmaxf(dv * (a0.x + a1v.x + a2.x + a3.x + dv * self.x) + b.x, 0.f);
    o.y = fmaxf(dv * (a0.y + a1v.y + a2.y + a3.y + dv * self.y) + b.y, 0.f);
    o.z = fmaxf(dv * (a0.z + a1v.z + a2.z + a3.z + dv * self.z) + b.z, 0.f);
    o.w = fmaxf(dv * (a0.w + a1v.w + a2.w + a3.w + dv * self.w) + b.w, 0.f);
    *((float4*)d_a1 + (size_t)n * 32 + lane) = o;
}

// ---------------- GEMM2 (mma.sync bf16, 3-pass): g2 = (a1 @ W2) * dinv ----------------
__global__ __launch_bounds__(256, 2) void gemm2_mma_kernel() {
    __shared__ __nv_bfloat16 sAh[128 * PK], sAl[128 * PK];
    __shared__ __nv_bfloat16 sBh[N2_PAD * PK], sBl[N2_PAD * PK];

    const int tid  = threadIdx.x;
    const int lane = tid & 31;
    const int w    = tid >> 5;
    const int wm   = w & 3;
    const int wn   = w >> 2;
    const int block_row = blockIdx.x * 128;

    const uint32_t uAh = smem_u32(sAh), uAl = smem_u32(sAl);
    const uint32_t uBh = smem_u32(sBh), uBl = smem_u32(sBl);

    float acc[2][4][4];
#pragma unroll
    for (int mt = 0; mt < 2; mt++)
#pragma unroll
        for (int nt = 0; nt < 4; nt++)
#pragma unroll
            for (int j = 0; j < 4; j++) acc[mt][nt][j] = 0.f;

    for (int kt = 0; kt < HID_F / 32; kt++) {
        __syncthreads();
#pragma unroll
        for (int i = 0; i < 4; i++) {
            int q  = tid + i * 256;
            int r  = q >> 3;
            int c4 = (q & 7) * 4;
            int grow = block_row + r;
            float4 v = make_float4(0.f, 0.f, 0.f, 0.f);
            if (grow < N_NODES)
                v = *(const float4*)(d_a1 + (size_t)grow * HID_F + kt * 32 + c4);
            __nv_bfloat162 h01, h23, l01, l23;
            h01.x = __float2bfloat16(v.x); h01.y = __float2bfloat16(v.y);
            h23.x = __float2bfloat16(v.z); h23.y = __float2bfloat16(v.w);
            l01.x = __float2bfloat16(v.x - __bfloat162float(h01.x));
            l01.y = __float2bfloat16(v.y - __bfloat162float(h01.y));
            l23.x = __float2bfloat16(v.z - __bfloat162float(h23.x));
            l23.y = __float2bfloat16(v.w - __bfloat162float(h23.y));
            *(__nv_bfloat162*)&sAh[r * PK + c4]     = h01;
            *(__nv_bfloat162*)&sAh[r * PK + c4 + 2] = h23;
            *(__nv_bfloat162*)&sAl[r * PK + c4]     = l01;
            *(__nv_bfloat162*)&sAl[r * PK + c4 + 2] = l23;
        }
        {
            int q  = tid;
            int n  = q >> 2;
            int kk = (q & 3) * 8;
            uint4 hv = *(const uint4*)(d_w2t_hi + (size_t)n * HID_F + kt * 32 + kk);
            uint4 lv = *(const uint4*)(d_w2t_lo + (size_t)n * HID_F + kt * 32 + kk);
            *(uint4*)&sBh[n * PK + kk] = hv;
            *(uint4*)&sBl[n * PK + kk] = lv;
        }
        __syncthreads();

#pragma unroll
        for (int ks = 0; ks < 2; ks++) {
            uint32_t ah[2][4], al[2][4];
#pragma unroll
            for (int mt = 0; mt < 2; mt++) {
                int row  = wm * 32 + mt * 16 + (lane & 15);
                int koff = ks * 16 + (lane >> 4) * 8;
                uint32_t off = (uint32_t)(row * PK + koff) * 2;
                ldmatrix_x4(ah[mt], uAh + off);
                ldmatrix_x4(al[mt], uAl + off);
            }
#pragma unroll
            for (int g = 0; g < 2; g++) {
                int n    = wn * 32 + g * 16 + ((lane >> 4) & 1) * 8 + (lane & 7);
                int koff = ks * 16 + ((lane >> 3) & 1) * 8;
                uint32_t off = (uint32_t)(n * PK + koff) * 2;
                uint32_t bh[4], bl[4];
                ldmatrix_x4(bh, uBh + off);
                ldmatrix_x4(bl, uBl + off);
#pragma unroll
                for (int t = 0; t < 2; t++) {
                    int nt = 2 * g + t;
#pragma unroll
                    for (int mt = 0; mt < 2; mt++) {
                        mma_bf16(acc[mt][nt], ah[mt], bh[2 * t], bh[2 * t + 1]);
                        mma_bf16(acc[mt][nt], ah[mt], bl[2 * t], bl[2 * t + 1]);
                        mma_bf16(acc[mt][nt], al[mt], bh[2 * t], bh[2 * t + 1]);
                    }
                }
            }
        }
    }

#pragma unroll
    for (int mt = 0; mt < 2; mt++) {
        int r0 = block_row + wm * 32 + mt * 16 + (lane >> 2);
        int r1 = r0 + 8;
        float dv0 = (r0 < N_NODES) ? d_dinv[r0] : 0.f;
        float dv1 = (r1 < N_NODES) ? d_dinv[r1] : 0.f;
#pragma unroll
        for (int nt = 0; nt < 4; nt++) {
            int col = wn * 32 + nt * 8 + (lane & 3) * 2;
            if (col < OUT_F) {
                if (r0 < N_NODES) {
                    float2 o = make_float2(acc[mt][nt][0] * dv0, acc[mt][nt][1] * dv0);
                    *(float2*)(d_g2 + (size_t)r0 * OUT_F + col) = o;
                }
                if (r1 < N_NODES) {
                    float2 o = make_float2(acc[mt][nt][2] * dv1, acc[mt][nt][3] * dv1);
                    *(float2*)(d_g2 + (size_t)r1 * OUT_F + col) = o;
                }
            }
        }
    }
}

// ---------------- gather2 + log_softmax fused ----------------
__global__ __launch_bounds__(256) void gather2_kernel(const float* __restrict__ b2,
                                                      float* __restrict__ out) {
    int n    = (blockIdx.x * blockDim.x + threadIdx.x) >> 5;
    int lane = threadIdx.x & 31;
    if (n >= N_NODES) return;
    int start = d_rowptr[n];
    int end   = d_rowptr[n + 1];
    int deg   = end - start;

    const float4* G = (const float4*)d_g2;
    int sub  = lane / 10;
    int comp = lane % 10;
    bool active = lane < 30;

    float4 a = make_float4(0.f, 0.f, 0.f, 0.f);
    for (int base = 0; base < deg; base += 3) {
        int idx = base + sub;
        if (active && idx < deg) {
            int s = d_csr_src[start + idx];
            float4 v = G[(size_t)s * 10 + comp];
            a.x += v.x; a.y += v.y; a.z += v.z; a.w += v.w;
        }
    }
#pragma unroll
    for (int off = 10; off <= 20; off += 10) {
        float vx = __shfl_sync(0xFFFFFFFFu, a.x, lane + off < 32 ? lane + off : lane);
        float vy = __shfl_sync(0xFFFFFFFFu, a.y, lane + off < 32 ? lane + off : lane);
        float vz = __shfl_sync(0xFFFFFFFFu, a.z, lane + off < 32 ? lane + off : lane);
        float vw = __shfl_sync(0xFFFFFFFFu, a.w, lane + off < 32 ? lane + off : lane);
        if (lane < 10 && lane + off < 30) { a.x += vx; a.y += vy; a.z += vz; a.w += vw; }
    }

    float dv = d_dinv[n];
    float4 vals = make_float4(-FLT_MAX, -FLT_MAX, -FLT_MAX, -FLT_MAX);
    if (lane < 10) {
        float4 self = G[(size_t)n * 10 + lane];
        float4 b = *(const float4*)(b2 + lane * 4);
        vals.x = dv * (a.x + self.x) + b.x;
        vals.y = dv * (a.y + self.y) + b.y;
        vals.z = dv * (a.z + self.z) + b.z;
        vals.w = dv * (a.w + self.w) + b.w;
    }
    float m = fmaxf(fmaxf(vals.x, vals.y), fmaxf(vals.z, vals.w));
#pragma unroll
    for (int o = 16; o > 0; o >>= 1) m = fmaxf(m, __shfl_xor_sync(0xFFFFFFFFu, m, o));
    float esum = 0.f;
    if (lane < 10) {
        esum = __expf(vals.x - m) + __expf(vals.y - m) +
               __expf(vals.z - m) + __expf(vals.w - m);
    }
#pragma unroll
    for (int o = 16; o > 0; o >>= 1) esum += __shfl_xor_sync(0xFFFFFFFFu, esum, o);

    float ls = m + __logf(esum);
    if (lane < 10) {
        float4 o4 = make_float4(vals.x - ls, vals.y - ls, vals.z - ls, vals.w - ls);
        *((float4*)(out + (size_t)n * OUT_F) + lane) = o4;
    }
}

// ---------------- launch: fork CSR chain onto side stream, join before gather1 ----------------
extern "C" void kernel_launch(void* const* d_in, const int* in_sizes, int n_in,
                              void* d_out, int out_size) {
    const float* x   = (const float*)d_in[0];
    const int*   ei  = (const int*)d_in[1];
    const float* W1  = (const float*)d_in[2];
    const float* b1  = (const float*)d_in[3];
    const float* W2  = (const float*)d_in[4];
    const float* b2  = (const float*)d_in[5];
    float*       out = (float*)d_out;

    const int E = in_sizes[1] / 2;
    const int* src = ei;
    const int* dst = ei + E;

    static cudaStream_t s2 = nullptr;
    static cudaEvent_t evA = nullptr, evB = nullptr;
    if (s2 == nullptr) {
        cudaStreamCreateWithFlags(&s2, cudaStreamNonBlocking);
        cudaEventCreateWithFlags(&evA, cudaEventDisableTiming);
        cudaEventCreateWithFlags(&evB, cudaEventDisableTiming);
    }

    // fork: side stream builds CSR + dinv while main stream does W-split + GEMM1
    cudaEventRecord(evA, cudaStreamPerThread);
    cudaStreamWaitEvent(s2, evA, 0);

    zero_deg_kernel<<<(N_NODES + 255) / 256, 256, 0, s2>>>();
    count_deg_kernel<<<1536, 256, 0, s2>>>(dst, E);
    dinv_blocksum_kernel<<<N_SCAN_BLOCKS, SCAN_B, 0, s2>>>();
    scan_tops_kernel<<<1, 128, 0, s2>>>();
    rowptr_kernel<<<N_SCAN_BLOCKS, SCAN_B, 0, s2>>>();
    fill_kernel<<<1024, 256, 0, s2>>>(src, dst, E);
    cudaEventRecord(evB, s2);

    prep_w_kernel<<<256 + 32, 256>>>(W1, W2);
    gemm1_mma_kernel<<<GEMM1_BLOCKS, 256>>>(x);

    // join
    cudaStreamWaitEvent(cudaStreamPerThread, evB, 0);

    gather1_kernel<<<(N_NODES * 32 + 255) / 256, 256>>>(b1);
    gemm2_mma_kernel<<<(N_NODES + 127) / 128, 256>>>();
    gather2_kernel<<<(N_NODES * 32 + 255) / 256, 256>>>(b2, out);
}

// round 15
// speedup vs baseline: 1.0252x; 1.0252x over previous
#include <cuda_runtime.h>
#include <cuda_bf16.h>
#include <math.h>
#include <float.h>
#include <stdint.h>

#define N_NODES 100000
#define E_MAX   1600000
#define IN_F    512
#define HID_F   128
#define OUT_F   40
#define N2_PAD  64

#define SCAN_B  1024
#define N_SCAN_BLOCKS ((N_NODES + SCAN_B - 1) / SCAN_B)   // 98

// ---------------- scratch (device globals; no allocation allowed) ----------------
__device__ int   d_deg    [N_NODES];
__device__ int   d_rowptr [N_NODES + 1];
__device__ int   d_cursor [N_NODES];
__device__ int   d_csr_src[E_MAX];
__device__ int   d_blocksum[N_SCAN_BLOCKS];
__device__ int   d_blockoff[N_SCAN_BLOCKS + 1];
__device__ float d_dinv[N_NODES];
__device__ float d_g1  [(size_t)N_NODES * HID_F];   // raw h1 = X@W1 (unscaled)
__device__ float d_a1  [(size_t)N_NODES * HID_F];
__device__ float d_g2  [(size_t)N_NODES * OUT_F];
__device__ __nv_bfloat16 d_w1t_hi[(size_t)HID_F * IN_F];   // [n][k]
__device__ __nv_bfloat16 d_w1t_lo[(size_t)HID_F * IN_F];
__device__ __nv_bfloat16 d_w2t_hi[(size_t)N2_PAD * HID_F]; // [n][k], zero-padded n>=40
__device__ __nv_bfloat16 d_w2t_lo[(size_t)N2_PAD * HID_F];

// ---------------- helpers ----------------
__device__ __forceinline__ uint32_t smem_u32(const void* p) {
    uint32_t a;
    asm("{ .reg .u64 t; cvta.to.shared.u64 t, %1; cvt.u32.u64 %0, t; }" : "=r"(a) : "l"(p));
    return a;
}
__device__ __forceinline__ void ldmatrix_x4(uint32_t* d, uint32_t addr) {
    asm volatile("ldmatrix.sync.aligned.m8n8.x4.shared.b16 {%0,%1,%2,%3}, [%4];"
                 : "=r"(d[0]), "=r"(d[1]), "=r"(d[2]), "=r"(d[3]) : "r"(addr));
}
__device__ __forceinline__ void mma_bf16(float* c, const uint32_t* a, uint32_t b0, uint32_t b1) {
    asm volatile("mma.sync.aligned.m16n8k16.row.col.f32.bf16.bf16.f32 "
                 "{%0,%1,%2,%3}, {%4,%5,%6,%7}, {%8,%9}, {%0,%1,%2,%3};"
                 : "+f"(c[0]), "+f"(c[1]), "+f"(c[2]), "+f"(c[3])
                 : "r"(a[0]), "r"(a[1]), "r"(a[2]), "r"(a[3]), "r"(b0), "r"(b1));
}
__device__ __forceinline__ void cp_async16(uint32_t saddr, const void* gptr) {
    asm volatile("cp.async.cg.shared.global [%0], [%1], 16;" :: "r"(saddr), "l"(gptr));
}
#define CP_COMMIT() asm volatile("cp.async.commit_group;" ::: "memory")
#define CP_WAIT0()  asm volatile("cp.async.wait_group 0;" ::: "memory")
#define CP_WAIT1()  asm volatile("cp.async.wait_group 1;" ::: "memory")

// ---------------- CSR chain kernels (side stream) ----------------
__global__ void zero_deg_kernel() {
    int i = blockIdx.x * blockDim.x + threadIdx.x;
    if (i < N_NODES) d_deg[i] = 0;
}

__global__ void count_deg_kernel(const int* __restrict__ dst, int E) {
    int i = blockIdx.x * blockDim.x + threadIdx.x;
    int stride = gridDim.x * blockDim.x;
    for (; i < E; i += stride) atomicAdd(&d_deg[dst[i]], 1);
}

__global__ __launch_bounds__(SCAN_B) void dinv_blocksum_kernel() {
    __shared__ int sh[SCAN_B / 32];
    int i = blockIdx.x * SCAN_B + threadIdx.x;
    int v = 0;
    if (i < N_NODES) {
        v = d_deg[i];
        d_dinv[i] = rsqrtf((float)v + 1.0f);
    }
    int s = v;
#pragma unroll
    for (int o = 16; o > 0; o >>= 1) s += __shfl_xor_sync(0xFFFFFFFFu, s, o);
    if ((threadIdx.x & 31) == 0) sh[threadIdx.x >> 5] = s;
    __syncthreads();
    if (threadIdx.x < SCAN_B / 32) {
        int t = sh[threadIdx.x];
#pragma unroll
        for (int o = 16; o > 0; o >>= 1) t += __shfl_xor_sync(0xFFFFFFFFu, t, o);
        if (threadIdx.x == 0) d_blocksum[blockIdx.x] = t;
    }
}

__global__ __launch_bounds__(128) void scan_tops_kernel() {
    __shared__ int sh[N_SCAN_BLOCKS];
    int tid = threadIdx.x;
    if (tid < N_SCAN_BLOCKS) sh[tid] = d_blocksum[tid];
    __syncthreads();
    if (tid == 0) {
        int run = 0;
        for (int i = 0; i < N_SCAN_BLOCKS; i++) { int t = sh[i]; sh[i] = run; run += t; }
        d_blockoff[N_SCAN_BLOCKS] = run;
    }
    __syncthreads();
    if (tid < N_SCAN_BLOCKS) d_blockoff[tid] = sh[tid];
}

__global__ __launch_bounds__(SCAN_B) void rowptr_kernel() {
    __shared__ int sh[SCAN_B];
    int tid = threadIdx.x;
    int i = blockIdx.x * SCAN_B + tid;
    int v = (i < N_NODES) ? d_deg[i] : 0;
    sh[tid] = v;
    __syncthreads();
    for (int off = 1; off < SCAN_B; off <<= 1) {
        int t = (tid >= off) ? sh[tid - off] : 0;
        __syncthreads();
        sh[tid] += t;
        __syncthreads();
    }
    if (i < N_NODES) {
        int excl = sh[tid] - v;
        d_rowptr[i] = d_blockoff[blockIdx.x] + excl;
        d_cursor[i] = 0;
    }
    if (i == N_NODES - 1) d_rowptr[N_NODES] = d_blockoff[N_SCAN_BLOCKS];
}

__global__ void fill_kernel(const int* __restrict__ src, const int* __restrict__ dst, int E) {
    int i = blockIdx.x * blockDim.x + threadIdx.x;
    int stride = gridDim.x * blockDim.x;
    for (; i < E; i += stride) {
        int d = dst[i];
        int pos = d_rowptr[d] + atomicAdd(&d_cursor[d], 1);
        d_csr_src[pos] = src[i];
    }
}

// ---------------- weight splits ----------------
__global__ void prep_w_kernel(const float* __restrict__ W1, const float* __restrict__ W2) {
    int b = blockIdx.x;
    if (b < 256) {
        int i = b * blockDim.x + threadIdx.x;   // 0..65535
        int k = i / HID_F, n = i % HID_F;
        float v = W1[i];
        __nv_bfloat16 hi = __float2bfloat16(v);
        d_w1t_hi[(size_t)n * IN_F + k] = hi;
        d_w1t_lo[(size_t)n * IN_F + k] = __float2bfloat16(v - __bfloat162float(hi));
    } else {
        int i = (b - 256) * blockDim.x + threadIdx.x;  // 0..8191
        int k = i / N2_PAD, n = i % N2_PAD;
        float v = (n < OUT_F) ? W2[k * OUT_F + n] : 0.f;
        __nv_bfloat16 hi = __float2bfloat16(v);
        d_w2t_hi[(size_t)n * HID_F + k] = hi;
        d_w2t_lo[(size_t)n * HID_F + k] = __float2bfloat16(v - __bfloat162float(hi));
    }
}

// ---------------- GEMM1 (mma.sync bf16, 3-pass, cp.async B double-buffer) ----------------
// smem layout (dynamic): Ah[10240] Al[10240] | buf0: Bh Bl | buf1: Bh Bl
#define PK 40
#define TILE_BYTES  (128 * PK * 2)            // 10240
#define BUF_STRIDE  (2 * TILE_BYTES)          // Bh+Bl
#define GEMM1_SMEM  (2 * TILE_BYTES + 2 * BUF_STRIDE)   // 61440
#define GEMM1_BLOCKS ((N_NODES + 127) / 128)  // 782
#define NKT (IN_F / 32)                       // 16

__device__ __forceinline__ void issue_B1(int kt, uint32_t uBh, uint32_t uBl, int tid) {
    int n    = tid >> 1;            // row 0..127
    int half = (tid & 1) * 2;       // chunk pair {0,1} or {2,3}
    const char* gh = (const char*)(d_w1t_hi + (size_t)n * IN_F + kt * 32) + half * 16;
    const char* gl = (const char*)(d_w1t_lo + (size_t)n * IN_F + kt * 32) + half * 16;
    uint32_t sh = uBh + (uint32_t)(n * (PK * 2)) + half * 16;
    uint32_t sl = uBl + (uint32_t)(n * (PK * 2)) + half * 16;
    cp_async16(sh, gh);       cp_async16(sh + 16, gh + 16);
    cp_async16(sl, gl);       cp_async16(sl + 16, gl + 16);
}

__global__ __launch_bounds__(256, 2) void gemm1_mma_kernel(const float* __restrict__ X) {
    extern __shared__ char smem[];
    const uint32_t uAh = smem_u32(smem);
    const uint32_t uAl = uAh + TILE_BYTES;
    const uint32_t uB  = uAl + TILE_BYTES;

    const int tid  = threadIdx.x;
    const int lane = tid & 31;
    const int w    = tid >> 5;
    const int wm   = w & 3;
    const int wn   = w >> 2;
    const int block_row = blockIdx.x * 128;

    float acc[2][8][4];
#pragma unroll
    for (int mt = 0; mt < 2; mt++)
#pragma unroll
        for (int nt = 0; nt < 8; nt++)
#pragma unroll
            for (int j = 0; j < 4; j++) acc[mt][nt][j] = 0.f;

    // prologue: prefetch B chunk 0 into buffer 0
    issue_B1(0, uB, uB + TILE_BYTES, tid);
    CP_COMMIT();

    for (int kt = 0; kt < NKT; kt++) {
        __syncthreads();   // previous compute done (A smem + the B buffer we are about to refill)

        // prefetch next B chunk into the other buffer
        if (kt + 1 < NKT) {
            uint32_t nb = uB + ((kt + 1) & 1) * BUF_STRIDE;
            issue_B1(kt + 1, nb, nb + TILE_BYTES, tid);
            CP_COMMIT();
        }

        // A: 128 rows x 32 fp32 -> bf16 hi/lo into smem
#pragma unroll
        for (int i = 0; i < 4; i++) {
            int q  = tid + i * 256;
            int r  = q >> 3;
            int c4 = (q & 7) * 4;
            int grow = block_row + r;
            float4 v = make_float4(0.f, 0.f, 0.f, 0.f);
            if (grow < N_NODES)
                v = *(const float4*)(X + (size_t)grow * IN_F + kt * 32 + c4);
            __nv_bfloat162 h01, h23, l01, l23;
            h01.x = __float2bfloat16(v.x); h01.y = __float2bfloat16(v.y);
            h23.x = __float2bfloat16(v.z); h23.y = __float2bfloat16(v.w);
            l01.x = __float2bfloat16(v.x - __bfloat162float(h01.x));
            l01.y = __float2bfloat16(v.y - __bfloat162float(h01.y));
            l23.x = __float2bfloat16(v.z - __bfloat162float(h23.x));
            l23.y = __float2bfloat16(v.w - __bfloat162float(h23.y));
            uint32_t offA = (uint32_t)(r * PK + c4) * 2;
            uint2 hu = make_uint2(*(uint32_t*)&h01, *(uint32_t*)&h23);
            uint2 lu = make_uint2(*(uint32_t*)&l01, *(uint32_t*)&l23);
            asm volatile("st.shared.v2.b32 [%0], {%1, %2};" :: "r"(uAh + offA), "r"(hu.x), "r"(hu.y) : "memory");
            asm volatile("st.shared.v2.b32 [%0], {%1, %2};" :: "r"(uAl + offA), "r"(lu.x), "r"(lu.y) : "memory");
        }

        // ensure B(kt) landed (one newer group may stay in flight)
        if (kt + 1 < NKT) CP_WAIT1(); else CP_WAIT0();
        __syncthreads();

        const uint32_t uBh = uB + (kt & 1) * BUF_STRIDE;
        const uint32_t uBl = uBh + TILE_BYTES;

#pragma unroll
        for (int ks = 0; ks < 2; ks++) {
            uint32_t ah[2][4], al[2][4];
#pragma unroll
            for (int mt = 0; mt < 2; mt++) {
                int row  = wm * 32 + mt * 16 + (lane & 15);
                int koff = ks * 16 + (lane >> 4) * 8;
                uint32_t off = (uint32_t)(row * PK + koff) * 2;
                ldmatrix_x4(ah[mt], uAh + off);
                ldmatrix_x4(al[mt], uAl + off);
            }
#pragma unroll
            for (int g = 0; g < 4; g++) {
                int n    = wn * 64 + g * 16 + ((lane >> 4) & 1) * 8 + (lane & 7);
                int koff = ks * 16 + ((lane >> 3) & 1) * 8;
                uint32_t off = (uint32_t)(n * PK + koff) * 2;
                uint32_t bh[4], bl[4];
                ldmatrix_x4(bh, uBh + off);
                ldmatrix_x4(bl, uBl + off);
#pragma unroll
                for (int t = 0; t < 2; t++) {
                    int nt = 2 * g + t;
#pragma unroll
                    for (int mt = 0; mt < 2; mt++) {
                        mma_bf16(acc[mt][nt], ah[mt], bh[2 * t], bh[2 * t + 1]);
                        mma_bf16(acc[mt][nt], ah[mt], bl[2 * t], bl[2 * t + 1]);
                        mma_bf16(acc[mt][nt], al[mt], bh[2 * t], bh[2 * t + 1]);
                    }
                }
            }
        }
    }

#pragma unroll
    for (int mt = 0; mt < 2; mt++) {
        int r0 = block_row + wm * 32 + mt * 16 + (lane >> 2);
        int r1 = r0 + 8;
#pragma unroll
        for (int nt = 0; nt < 8; nt++) {
            int col = wn * 64 + nt * 8 + (lane & 3) * 2;
            if (r0 < N_NODES) {
                float2 o = make_float2(acc[mt][nt][0], acc[mt][nt][1]);
                *(float2*)(d_g1 + (size_t)r0 * HID_F + col) = o;
            }
            if (r1 < N_NODES) {
                float2 o = make_float2(acc[mt][nt][2], acc[mt][nt][3]);
                *(float2*)(d_g1 + (size_t)r1 * HID_F + col) = o;
            }
        }
    }
}

// ---------------- gather1: a1 = relu(dinv_d*(sum dinv_s*h1[s] + dinv_d*h1[d]) + b1) ----------------
__global__ __launch_bounds__(256) void gather1_kernel(const float* __restrict__ b1) {
    int n    = (blockIdx.x * blockDim.x + threadIdx.x) >> 5;
    int lane = threadIdx.x & 31;
    if (n >= N_NODES) return;
    int e   = d_rowptr[n];
    int end = d_rowptr[n + 1];

    const float4* G = (const float4*)d_g1;
    float4 a0 = make_float4(0.f, 0.f, 0.f, 0.f);
    float4 a1v = make_float4(0.f, 0.f, 0.f, 0.f);
    float4 a2 = make_float4(0.f, 0.f, 0.f, 0.f);
    float4 a3 = make_float4(0.f, 0.f, 0.f, 0.f);

    for (; e + 3 < end; e += 4) {
        int s0 = d_csr_src[e];
        int s1 = d_csr_src[e + 1];
        int s2 = d_csr_src[e + 2];
        int s3 = d_csr_src[e + 3];
        float ds0 = d_dinv[s0], ds1 = d_dinv[s1], ds2 = d_dinv[s2], ds3 = d_dinv[s3];
        float4 v0 = G[(size_t)s0 * 32 + lane];
        float4 v1 = G[(size_t)s1 * 32 + lane];
        float4 v2 = G[(size_t)s2 * 32 + lane];
        float4 v3 = G[(size_t)s3 * 32 + lane];
        a0.x = fmaf(v0.x, ds0, a0.x); a0.y = fmaf(v0.y, ds0, a0.y);
        a0.z = fmaf(v0.z, ds0, a0.z); a0.w = fmaf(v0.w, ds0, a0.w);
        a1v.x = fmaf(v1.x, ds1, a1v.x); a1v.y = fmaf(v1.y, ds1, a1v.y);
        a1v.z = fmaf(v1.z, ds1, a1v.z); a1v.w = fmaf(v1.w, ds1, a1v.w);
        a2.x = fmaf(v2.x, ds2, a2.x); a2.y = fmaf(v2.y, ds2, a2.y);
        a2.z = fmaf(v2.z, ds2, a2.z); a2.w = fmaf(v2.w, ds2, a2.w);
        a3.x = fmaf(v3.x, ds3, a3.x); a3.y = fmaf(v3.y, ds3, a3.y);
        a3.z = fmaf(v3.z, ds3, a3.z); a3.w = fmaf(v3.w, ds3, a3.w);
    }
    for (; e < end; e++) {
        int s0 = d_csr_src[e];
        float ds0 = d_dinv[s0];
        float4 v0 = G[(size_t)s0 * 32 + lane];
        a0.x = fmaf(v0.x, ds0, a0.x); a0.y = fmaf(v0.y, ds0, a0.y);
        a0.z = fmaf(v0.z, ds0, a0.z); a0.w = fmaf(v0.w, ds0, a0.w);
    }
    float4 self = G[(size_t)n * 32 + lane];
    float dv = d_dinv[n];
    float4 b = *(const float4*)(b1 + lane * 4);
    float4 o;
    o.x = fmaxf(dv * (a0.x + a1v.x + a2.x + a3.x + dv * self.x) + b.x, 0.f);
    o.y = fmaxf(dv * (a0.y + a1v.y + a2.y + a3.y + dv * self.y) + b.y, 0.f);
    o.z = fmaxf(dv * (a0.z + a1v.z + a2.z + a3.z + dv * self.z) + b.z, 0.f);
    o.w = fmaxf(dv * (a0.w + a1v.w + a2.w + a3.w + dv * self.w) + b.w, 0.f);
    *((float4*)d_a1 + (size_t)n * 32 + lane) = o;
}

// ---------------- GEMM2 (mma.sync bf16, 3-pass): g2 = (a1 @ W2) * dinv ----------------
__global__ __launch_bounds__(256, 2) void gemm2_mma_kernel() {
    __shared__ __nv_bfloat16 sAh[128 * PK], sAl[128 * PK];
    __shared__ __nv_bfloat16 sBh[N2_PAD * PK], sBl[N2_PAD * PK];

    const int tid  = threadIdx.x;
    const int lane = tid & 31;
    const int w    = tid >> 5;
    const int wm   = w & 3;
    const int wn   = w >> 2;
    const int block_row = blockIdx.x * 128;

    const uint32_t uAh = smem_u32(sAh), uAl = smem_u32(sAl);
    const uint32_t uBh = smem_u32(sBh), uBl = smem_u32(sBl);

    float acc[2][4][4];
#pragma unroll
    for (int mt = 0; mt < 2; mt++)
#pragma unroll
        for (int nt = 0; nt < 4; nt++)
#pragma unroll
            for (int j = 0; j < 4; j++) acc[mt][nt][j] = 0.f;

    for (int kt = 0; kt < HID_F / 32; kt++) {
        __syncthreads();
#pragma unroll
        for (int i = 0; i < 4; i++) {
            int q  = tid + i * 256;
            int r  = q >> 3;
            int c4 = (q & 7) * 4;
            int grow = block_row + r;
            float4 v = make_float4(0.f, 0.f, 0.f, 0.f);
            if (grow < N_NODES)
                v = *(const float4*)(d_a1 + (size_t)grow * HID_F + kt * 32 + c4);
            __nv_bfloat162 h01, h23, l01, l23;
            h01.x = __float2bfloat16(v.x); h01.y = __float2bfloat16(v.y);
            h23.x = __float2bfloat16(v.z); h23.y = __float2bfloat16(v.w);
            l01.x = __float2bfloat16(v.x - __bfloat162float(h01.x));
            l01.y = __float2bfloat16(v.y - __bfloat162float(h01.y));
            l23.x = __float2bfloat16(v.z - __bfloat162float(h23.x));
            l23.y = __float2bfloat16(v.w - __bfloat162float(h23.y));
            *(__nv_bfloat162*)&sAh[r * PK + c4]     = h01;
            *(__nv_bfloat162*)&sAh[r * PK + c4 + 2] = h23;
            *(__nv_bfloat162*)&sAl[r * PK + c4]     = l01;
            *(__nv_bfloat162*)&sAl[r * PK + c4 + 2] = l23;
        }
        {
            int q  = tid;
            int n  = q >> 2;
            int kk = (q & 3) * 8;
            uint4 hv = *(const uint4*)(d_w2t_hi + (size_t)n * HID_F + kt * 32 + kk);
            uint4 lv = *(const uint4*)(d_w2t_lo + (size_t)n * HID_F + kt * 32 + kk);
            *(uint4*)&sBh[n * PK + kk] = hv;
            *(uint4*)&sBl[n * PK + kk] = lv;
        }
        __syncthreads();

#pragma unroll
        for (int ks = 0; ks < 2; ks++) {
            uint32_t ah[2][4], al[2][4];
#pragma unroll
            for (int mt = 0; mt < 2; mt++) {
                int row  = wm * 32 + mt * 16 + (lane & 15);
                int koff = ks * 16 + (lane >> 4) * 8;
                uint32_t off = (uint32_t)(row * PK + koff) * 2;
                ldmatrix_x4(ah[mt], uAh + off);
                ldmatrix_x4(al[mt], uAl + off);
            }
#pragma unroll
            for (int g = 0; g < 2; g++) {
                int n    = wn * 32 + g * 16 + ((lane >> 4) & 1) * 8 + (lane & 7);
                int koff = ks * 16 + ((lane >> 3) & 1) * 8;
                uint32_t off = (uint32_t)(n * PK + koff) * 2;
                uint32_t bh[4], bl[4];
                ldmatrix_x4(bh, uBh + off);
                ldmatrix_x4(bl, uBl + off);
#pragma unroll
                for (int t = 0; t < 2; t++) {
                    int nt = 2 * g + t;
#pragma unroll
                    for (int mt = 0; mt < 2; mt++) {
                        mma_bf16(acc[mt][nt], ah[mt], bh[2 * t], bh[2 * t + 1]);
                        mma_bf16(acc[mt][nt], ah[mt], bl[2 * t], bl[2 * t + 1]);
                        mma_bf16(acc[mt][nt], al[mt], bh[2 * t], bh[2 * t + 1]);
                    }
                }
            }
        }
    }

#pragma unroll
    for (int mt = 0; mt < 2; mt++) {
        int r0 = block_row + wm * 32 + mt * 16 + (lane >> 2);
        int r1 = r0 + 8;
        float dv0 = (r0 < N_NODES) ? d_dinv[r0] : 0.f;
        float dv1 = (r1 < N_NODES) ? d_dinv[r1] : 0.f;
#pragma unroll
        for (int nt = 0; nt < 4; nt++) {
            int col = wn * 32 + nt * 8 + (lane & 3) * 2;
            if (col < OUT_F) {
                if (r0 < N_NODES) {
                    float2 o = make_float2(acc[mt][nt][0] * dv0, acc[mt][nt][1] * dv0);
                    *(float2*)(d_g2 + (size_t)r0 * OUT_F + col) = o;
                }
                if (r1 < N_NODES) {
                    float2 o = make_float2(acc[mt][nt][2] * dv1, acc[mt][nt][3] * dv1);
                    *(float2*)(d_g2 + (size_t)r1 * OUT_F + col) = o;
                }
            }
        }
    }
}

// ---------------- gather2 + log_softmax fused ----------------
__global__ __launch_bounds__(256) void gather2_kernel(const float* __restrict__ b2,
                                                      float* __restrict__ out) {
    int n    = (blockIdx.x * blockDim.x + threadIdx.x) >> 5;
    int lane = threadIdx.x & 31;
    if (n >= N_NODES) return;
    int start = d_rowptr[n];
    int end   = d_rowptr[n + 1];
    int deg   = end - start;

    const float4* G = (const float4*)d_g2;
    int sub  = lane / 10;
    int comp = lane % 10;
    bool active = lane < 30;

    float4 a = make_float4(0.f, 0.f, 0.f, 0.f);
    for (int base = 0; base < deg; base += 3) {
        int idx = base + sub;
        if (active && idx < deg) {
            int s = d_csr_src[start + idx];
            float4 v = G[(size_t)s * 10 + comp];
            a.x += v.x; a.y += v.y; a.z += v.z; a.w += v.w;
        }
    }
#pragma unroll
    for (int off = 10; off <= 20; off += 10) {
        float vx = __shfl_sync(0xFFFFFFFFu, a.x, lane + off < 32 ? lane + off : lane);
        float vy = __shfl_sync(0xFFFFFFFFu, a.y, lane + off < 32 ? lane + off : lane);
        float vz = __shfl_sync(0xFFFFFFFFu, a.z, lane + off < 32 ? lane + off : lane);
        float vw = __shfl_sync(0xFFFFFFFFu, a.w, lane + off < 32 ? lane + off : lane);
        if (lane < 10 && lane + off < 30) { a.x += vx; a.y += vy; a.z += vz; a.w += vw; }
    }

    float dv = d_dinv[n];
    float4 vals = make_float4(-FLT_MAX, -FLT_MAX, -FLT_MAX, -FLT_MAX);
    if (lane < 10) {
        float4 self = G[(size_t)n * 10 + lane];
        float4 b = *(const float4*)(b2 + lane * 4);
        vals.x = dv * (a.x + self.x) + b.x;
        vals.y = dv * (a.y + self.y) + b.y;
        vals.z = dv * (a.z + self.z) + b.z;
        vals.w = dv * (a.w + self.w) + b.w;
    }
    float m = fmaxf(fmaxf(vals.x, vals.y), fmaxf(vals.z, vals.w));
#pragma unroll
    for (int o = 16; o > 0; o >>= 1) m = fmaxf(m, __shfl_xor_sync(0xFFFFFFFFu, m, o));
    float esum = 0.f;
    if (lane < 10) {
        esum = __expf(vals.x - m) + __expf(vals.y - m) +
               __expf(vals.z - m) + __expf(vals.w - m);
    }
#pragma unroll
    for (int o = 16; o > 0; o >>= 1) esum += __shfl_xor_sync(0xFFFFFFFFu, esum, o);

    float ls = m + __logf(esum);
    if (lane < 10) {
        float4 o4 = make_float4(vals.x - ls, vals.y - ls, vals.z - ls, vals.w - ls);
        *((float4*)(out + (size_t)n * OUT_F) + lane) = o4;
    }
}

// ---------------- launch ----------------
// API call order puts gemm1 4th so the ncu window (-s 5 -c 1, empirically the
// 4th launch) profiles it next round.
extern "C" void kernel_launch(void* const* d_in, const int* in_sizes, int n_in,
                              void* d_out, int out_size) {
    const float* x   = (const float*)d_in[0];
    const int*   ei  = (const int*)d_in[1];
    const float* W1  = (const float*)d_in[2];
    const float* b1  = (const float*)d_in[3];
    const float* W2  = (const float*)d_in[4];
    const float* b2  = (const float*)d_in[5];
    float*       out = (float*)d_out;

    const int E = in_sizes[1] / 2;
    const int* src = ei;
    const int* dst = ei + E;

    static cudaStream_t s2 = nullptr;
    static cudaEvent_t evA = nullptr, evB = nullptr;
    if (s2 == nullptr) {
        cudaStreamCreateWithFlags(&s2, cudaStreamNonBlocking);
        cudaEventCreateWithFlags(&evA, cudaEventDisableTiming);
        cudaEventCreateWithFlags(&evB, cudaEventDisableTiming);
        cudaFuncSetAttribute(gemm1_mma_kernel,
                             cudaFuncAttributeMaxDynamicSharedMemorySize, GEMM1_SMEM);
    }

    // fork: side stream builds CSR + dinv while main stream does W-split + GEMM1
    cudaEventRecord(evA, cudaStreamPerThread);
    cudaStreamWaitEvent(s2, evA, 0);

    prep_w_kernel<<<256 + 32, 256>>>(W1, W2);                 // launch 1 (main)
    zero_deg_kernel<<<(N_NODES + 255) / 256, 256, 0, s2>>>(); // launch 2 (s2)
    count_deg_kernel<<<1536, 256, 0, s2>>>(dst, E);           // launch 3 (s2)
    gemm1_mma_kernel<<<GEMM1_BLOCKS, 256, GEMM1_SMEM>>>(x);   // launch 4 (main) <- profiled
    dinv_blocksum_kernel<<<N_SCAN_BLOCKS, SCAN_B, 0, s2>>>(); // 5
    scan_tops_kernel<<<1, 128, 0, s2>>>();                    // 6
    rowptr_kernel<<<N_SCAN_BLOCKS, SCAN_B, 0, s2>>>();        // 7
    fill_kernel<<<1024, 256, 0, s2>>>(src, dst, E);           // 8
    cudaEventRecord(evB, s2);

    // join
    cudaStreamWaitEvent(cudaStreamPerThread, evB, 0);

    gather1_kernel<<<(N_NODES * 32 + 255) / 256, 256>>>(b1);
    gemm2_mma_kernel<<<(N_NODES + 127) / 128, 256>>>();
    gather2_kernel<<<(N_NODES * 32 + 255) / 256, 256>>>(b2, out);
}